// round 9
// baseline (speedup 1.0000x reference)
#include <cuda_runtime.h>
#include <cuda_fp16.h>

#define FRAME   160
#define ORDER   16
#define EPS     1e-8f
#define FPW     4                 // frames per warp
#define WARPS   4
#define THREADS (WARPS * 32)      // 128
#define FPB     (WARPS * FPW)     // 16 frames per block
#define FSTRIDE 198               // floats per frame region: 16 pad | 160 | 16 pad | 6 slack
#define PSTRIDE 99                // float2 pairs per frame region (odd -> conflict-free LDS.64)

typedef unsigned long long u64;

__device__ __forceinline__ u64 pack2(float lo, float hi) {
    u64 r; asm("mov.b64 %0, {%1, %2};" : "=l"(r) : "f"(lo), "f"(hi));
    return r;
}
#define BAR_SYNC(id)   asm volatile("bar.sync %0, %1;"   :: "r"(id), "r"(THREADS) : "memory")
#define BAR_ARRIVE(id) asm volatile("bar.arrive %0, %1;" :: "r"(id), "r"(THREADS) : "memory")

__global__ __launch_bounds__(THREADS, 8)
void lpc_residual_kernel(const float* __restrict__ x,
                         float* __restrict__ out,
                         int nframes)
{
    __shared__ __align__(16) float sx[WARPS * FPW * FSTRIDE];   // 12672 B
    __shared__ float rS[32][17];        // full autocorr per frame
    __shared__ float aS[32][17];        // LPC coeffs per frame

    const int lane   = threadIdx.x & 31;
    const int wid    = threadIdx.x >> 5;
    const int frame0 = blockIdx.x * FPB + wid * FPW;            // this warp's first frame

    float* sw  = sx + wid * FPW * FSTRIDE;
    u64*   swp = (u64*)sw;

    // ---- zero pads: per frame, floats [0,16) and [176,192) => pairs [0,8) and [88,96) ----
    {
        int f = lane >> 3, c = lane & 7;
        swp[f * PSTRIDE + c]      = 0ull;
        swp[f * PSTRIDE + 88 + c] = 0ull;
    }

    // ---- stage input: 10x LDG.64 + 10x STS.64 per lane, coalesced & conflict-free ----
    {
        const float2* gx2 = (const float2*)(x + (long long)frame0 * FRAME);
        #pragma unroll
        for (int q = 0; q < 10; q++) {
            int idx = q * 32 + lane;               // float2 index within warp's 320
            int f;
            if (q == 2)      f = (lane < 16) ? 0 : 1;   // frame boundary crossings
            else if (q == 7) f = (lane < 16) ? 2 : 3;
            else             f = (q * 32) / 80;         // compile-time constant
            if (frame0 + f < nframes) {
                float2 v = gx2[idx];
                // shared pair index: f*99 + 8 + (idx - 80f) = idx + 8 + 19f
                swp[idx + 8 + 19 * f] = pack2(v.x, v.y);
            }
        }
    }
    __syncwarp();   // warp only reads its own staged frames below

    const int fl = lane >> 3;               // frame within warp (0..3)
    const int p  = lane & 7;                // sub-lane within frame (0..7)
    const int myFrame = wid * FPW + fl;     // frame index within block
    // pair index of float w[0] = x[20p] of this frame (float idx fl*198 + 16 + 20p)
    const int ubase = fl * PSTRIDE + 8 + 10 * p;
    const float2* swp2 = (const float2*)swp;

    __half2 HP[18];     // fp16 pair window v[-16..19] for the FIR correction

    {
        // ---- autocorr window w[0..35] via 18 LDS.64 (fp32) ----
        float w[36];
        #pragma unroll
        for (int j = 0; j < 18; j++) {
            float2 t = swp2[ubase + j];
            w[2 * j] = t.x; w[2 * j + 1] = t.y;
        }

        // ---- autocorrelation: r[k] = sum_m w[m] w[m+k]; full 3-stage butterfly ----
        #pragma unroll
        for (int k = 0; k <= ORDER; k++) {
            float acc = 0.0f;
            #pragma unroll
            for (int m = 0; m < 20; m++)
                acc = fmaf(w[m], w[m + k], acc);
            acc += __shfl_xor_sync(0xFFFFFFFFu, acc, 1);
            acc += __shfl_xor_sync(0xFFFFFFFFu, acc, 2);
            acc += __shfl_xor_sync(0xFFFFFFFFu, acc, 4);
            if (p == 0) rS[myFrame][k] = acc;
        }

        // ---- convert FIR window to half2: main pairs from registers, history from shared ----
        #pragma unroll
        for (int j = 0; j < 10; j++)
            HP[8 + j] = __floats2half2_rn(w[2 * j], w[2 * j + 1]);
    }
    #pragma unroll
    for (int j = 0; j < 8; j++) {
        float2 t = swp2[ubase - 8 + j];
        HP[j] = __floats2half2_rn(t.x, t.y);
    }

    if (wid == 0) {
        // ---- consumer: wait for all autocorrs, run Levinson (one frame per lane) ----
        BAR_SYNC(1);

        float rr[ORDER + 1];
        #pragma unroll
        for (int k = 0; k <= ORDER; k++)
            rr[k] = rS[lane][k];                // stride-17 (odd) -> conflict-free

        float a[ORDER + 1];
        a[0] = 1.0f;
        float e = (rr[0] != 0.0f) ? rr[0] : EPS;
        #pragma unroll
        for (int i = 1; i <= ORDER; i++) {
            float s0 = 0.f, s1 = 0.f, s2 = 0.f, s3 = 0.f;
            #pragma unroll
            for (int j = 1; j < i; j++) {
                switch ((j - 1) & 3) {
                    case 0: s0 = fmaf(a[j], rr[i - j], s0); break;
                    case 1: s1 = fmaf(a[j], rr[i - j], s1); break;
                    case 2: s2 = fmaf(a[j], rr[i - j], s2); break;
                    default: s3 = fmaf(a[j], rr[i - j], s3); break;
                }
            }
            float acc = rr[i] - ((s0 + s1) + (s2 + s3));
            float kk = __fdividef(acc, e);
            float tn[ORDER + 1];
            #pragma unroll
            for (int j = 1; j < i; j++)
                tn[j] = fmaf(-kk, a[i - j], a[j]);
            #pragma unroll
            for (int j = 1; j < i; j++)
                a[j] = tn[j];
            a[i] = kk;
            e = fmaxf(fmaf(-kk, acc, e), EPS);   // e*(1-k^2) = e - k*acc
        }
        #pragma unroll
        for (int k = 1; k <= ORDER; k++) aS[lane][k] = a[k];

        BAR_ARRIVE(2);
        __syncwarp();       // make warp-0's own aS stores visible to its other lanes
    } else {
        BAR_ARRIVE(1);      // autocorrs published; don't wait for Levinson to start
    }

    if (wid != 0) BAR_SYNC(2);   // wait for coefficients

    // ---- packed fp16 coefficients: aPe[c]=(a2c,a2c), aPo[c]=(a2c+1,a2c+1) ----
    __half2 aPe[9], aPo[8];
    #pragma unroll
    for (int c = 1; c <= 8; c++) aPe[c] = __float2half2_rn(aS[myFrame][2 * c]);
    #pragma unroll
    for (int c = 0; c < 8; c++)  aPo[c] = __float2half2_rn(aS[myFrame][2 * c + 1]);

    // ---- FIR (E/O half2 correction + fp32 a0 term):
    //   E[t] = sum_{c=1..8} aPe[c]*HP[8+t-c]      (even taps for outputs 2t, 2t+1)
    //   O[t] = sum_{c=0..7} aPo[c]*HP[7+t-c]      (odd taps of outputs 2t-1, 2t)
    //   y[2t]   = x[2t]   + E[t].lo + O[t].hi
    //   y[2t+1] = x[2t+1] + E[t].hi + O[t+1].lo
    const bool wr = (frame0 + fl) < nframes;
    float4* go4 = (float4*)(out + (long long)(frame0 + fl) * FRAME + 20 * p);

    __half2 Oprev = __hmul2(aPo[0], HP[7]);
    #pragma unroll
    for (int c = 1; c < 8; c++) Oprev = __hfma2(aPo[c], HP[7 - c], Oprev);

    float res[4];
    #pragma unroll
    for (int t = 0; t < 10; t++) {
        __half2 e = __hmul2(aPe[1], HP[7 + t]);
        #pragma unroll
        for (int c = 2; c <= 8; c++)
            e = __hfma2(aPe[c], HP[8 + t - c], e);

        __half2 o = __hmul2(aPo[0], HP[8 + t]);            // O[t+1]
        #pragma unroll
        for (int c = 1; c < 8; c++)
            o = __hfma2(aPo[c], HP[8 + t - c], o);

        // merged = (Oprev.hi, o.lo) via one PRMT; C = E + merged
        unsigned mo = __byte_perm(*(const unsigned*)&Oprev, *(const unsigned*)&o, 0x5432);
        __half2 cc = __hadd2(e, *(const __half2*)&mo);

        float2 xx = swp2[ubase + t];                       // fp32 a0 term (w[2t], w[2t+1])
        res[(2 * t) & 3]     = xx.x + __low2float(cc);
        res[(2 * t + 1) & 3] = xx.y + __high2float(cc);
        Oprev = o;

        if ((t & 1) && wr)
            go4[t >> 1] = make_float4(res[0], res[1], res[2], res[3]);
    }
}

extern "C" void kernel_launch(void* const* d_in, const int* in_sizes, int n_in,
                              void* d_out, int out_size)
{
    const float* x = (const float*)d_in[0];
    float* out = (float*)d_out;

    long long total = in_sizes[0];
    int nframes = (int)(total / FRAME);                 // 128000 for the given shape
    int blocks  = (nframes + FPB - 1) / FPB;            // 8000

    lpc_residual_kernel<<<blocks, THREADS>>>(x, out, nframes);
}